// round 16
// baseline (speedup 1.0000x reference)
#include <cuda_runtime.h>
#include <cstdint>

#define TSTEPS 15
__device__ float g_dp[2048 * 4096];
__device__ float g_part[8 * 2048 * 128];

typedef unsigned long long u64;
__device__ __forceinline__ u64 pk(float lo, float hi) {
    u64 d; asm("mov.b64 %0,{%1,%2};" : "=l"(d) : "f"(lo), "f"(hi)); return d;
}
__device__ __forceinline__ void upk(u64 v, float& lo, float& hi) {
    asm("mov.b64 {%0,%1},%2;" : "=f"(lo), "=f"(hi) : "l"(v));
}
__device__ __forceinline__ u64 f2(u64 a, u64 b, u64 c) {
    u64 d; asm("fma.rn.f32x2 %0,%1,%2,%3;" : "=l"(d) : "l"(a), "l"(b), "l"(c)); return d;
}
__device__ __forceinline__ u64 add2(u64 a, u64 b) {
    u64 d; asm("add.rn.f32x2 %0,%1,%2;" : "=l"(d) : "l"(a), "l"(b)); return d;
}
__device__ __forceinline__ void lds2(u64& a, u64& b, uint32_t addr) {
    asm volatile("ld.shared.v2.u64 {%0,%1},[%2];" : "=l"(a), "=l"(b) : "r"(addr));
}
__device__ __forceinline__ u64 lds1(uint32_t addr) {
    u64 a; asm volatile("ld.shared.b64 %0,[%1];" : "=l"(a) : "r"(addr)); return a;
}
__device__ __forceinline__ void sts2(uint32_t addr, u64 a, u64 b) {
    asm volatile("st.shared.v2.u64 [%0],{%1,%2};" :: "r"(addr), "l"(a), "l"(b));
}
__device__ __forceinline__ float lif_step(float& m, float cur, float beta, float thr) {
    float r = (m > thr) ? thr : 0.f;
    m = beta * m + (cur - r);
    return (m > thr) ? 1.f : 0.f;
}

// smem float offsets (R12 map)
#define SM_LT    0
#define SM_S1_0  4096
#define SM_S1_1  6144
#define SM_S1_2  8192
#define SM_PT_0  10240
#define SM_PT_1  12288
#define SM_PT_2  14336
#define SM_WG2   16384
#define SM_ST    18432
#define SM_XS    19456
#define SM_ROWL  20416
#define SM_AX    20480
#define SM_P1    20544
#define SM_Q1    20576
#define SM_BG1   20608
#define SM_PS1   20640
#define SM_CS1   20672
#define SM_P2    20704
#define SM_Q2    20768
#define SM_BG2   20832
#define SM_PS2   20896
#define SM_QS2   20960
#define SM_COEF  21024
#define SM_TOTAL 21040

__global__ void __launch_bounds__(256, 1)
main_kernel(const float* __restrict__ L, const float* __restrict__ X,
            const float* __restrict__ Wproj, const float* __restrict__ bproj,
            const float* __restrict__ Wg1, const float* __restrict__ bg1,
            const float* __restrict__ Ws1, const float* __restrict__ bs1,
            const float* __restrict__ Wg2, const float* __restrict__ bg2,
            const float* __restrict__ Ws2, const float* __restrict__ bs2) {
    extern __shared__ float sm[];
    const uint32_t smb = (uint32_t)__cvta_generic_to_shared(sm);
    float* Lt = sm + SM_LT; float* Xs = sm + SM_XS; float* St = sm + SM_ST;
    float* rowL = sm + SM_ROWL; float* axs = sm + SM_AX; float* coef = sm + SM_COEF;

    const int tid = threadIdx.x;
    const int b = blockIdx.x;
    const float* Lb = L + (size_t)b * 4096;
    const float* Xb = X + (size_t)b * (TSTEPS * 64);

    {   // Lt transpose
        int n = tid >> 2, m0 = (tid & 3) * 16;
        #pragma unroll
        for (int q = 0; q < 4; q++) {
            float4 v = *(const float4*)(Lb + n * 64 + m0 + q * 4);
            Lt[(m0 + q * 4 + 0) * 64 + n] = v.x;
            Lt[(m0 + q * 4 + 1) * 64 + n] = v.y;
            Lt[(m0 + q * 4 + 2) * 64 + n] = v.z;
            Lt[(m0 + q * 4 + 3) * 64 + n] = v.w;
        }
    }
    for (int i = tid; i < TSTEPS * 64; i += 256) Xs[i] = Xb[i];
    #pragma unroll
    for (int k = 0; k < 8; k++)
        sm[SM_WG2 + tid + k * 256] = Wg2[tid + k * 256];
    if (tid < 32) {
        float p1 = 0.f, q1 = 0.f, ps1 = 0.f, cs1 = 0.f;
        #pragma unroll
        for (int k = 0; k < 16; k++) {
            p1  += Wproj[k] * Wg1[k * 32 + tid];
            q1  += bproj[k] * Wg1[k * 32 + tid];
            ps1 += Wproj[k] * Ws1[k * 32 + tid];
            cs1 += bproj[k] * Ws1[k * 32 + tid];
        }
        cs1 += bs1[tid];
        sm[SM_P1 + tid] = p1; sm[SM_Q1 + tid] = q1;
        sm[SM_PS1 + tid] = ps1; sm[SM_CS1 + tid] = cs1;
        sm[SM_BG1 + tid] = bg1[tid];
    }
    if (tid == 32) {
        float pw[TSTEPS]; pw[0] = 1.f;
        for (int k = 1; k < TSTEPS; k++) pw[k] = pw[k - 1] * 0.9f;
        float cs = 0.f;
        for (int tau = 0; tau < TSTEPS; tau++) {
            float late = 0.f, early = 0.f;
            for (int s = 10; s < 15; s++) if (s >= tau) late += pw[s - tau];
            for (int s = 0; s < 5; s++) if (s >= tau) early += pw[s - tau];
            float c = 0.2f * (late - early);
            coef[tau] = c; cs += c;
        }
        coef[15] = cs;
    }
    __syncthreads();

    if (tid < 64) {
        float p2 = 0.f, q2 = 0.f, ps2 = 0.f, qs2 = 0.f;
        #pragma unroll
        for (int f = 0; f < 32; f++) {
            float a = sm[SM_PS1 + f], c = sm[SM_CS1 + f];
            p2 += a * Wg2[f * 64 + tid]; q2 += c * Wg2[f * 64 + tid];
            ps2 += a * Ws2[f * 64 + tid]; qs2 += c * Ws2[f * 64 + tid];
        }
        qs2 += bs2[tid];
        sm[SM_P2 + tid] = p2; sm[SM_Q2 + tid] = q2;
        sm[SM_BG2 + tid] = bg2[tid];
        sm[SM_PS2 + tid] = ps2; sm[SM_QS2 + tid] = qs2;
    }
    #pragma unroll
    for (int k = 0; k < 4; k++) {
        int idx = tid + k * 256;
        int n = idx & 63, tt = idx >> 6;
        float acc = 0.f;
        if (tt < TSTEPS) {
            const float* xr = Xs + tt * 64;
            #pragma unroll 8
            for (int m = 0; m < 64; m++) acc += Lt[m * 64 + n] * xr[m];
            St[tt * 64 + n] = acc;
        } else {
            #pragma unroll 8
            for (int m = 0; m < 64; m++) acc += Lt[m * 64 + n];
            rowL[n] = acc;
        }
    }
    __syncthreads();

    const int lane = tid & 31, wA = tid >> 5;
    const int nR = (wA & 1) * 32 + (lane & 7) * 4;
    const int c0 = (wA >> 1) * 16 + (lane >> 3) * 4;
    // phase2 (256 threads): 4n x 2j x 3t tiles
    const int nq4 = (tid & 15) * 16;       // byte offset of 4-row quad
    const int jp  = (tid >> 4) * 2;        // j pair base (0..30)

    const float p1f = sm[SM_P1 + lane], q1f = sm[SM_Q1 + lane], bg1f = sm[SM_BG1 + lane];
    const u64 p1dup = pk(p1f, p1f);
    u64 base1p[4];
    #pragma unroll
    for (int i2 = 0; i2 < 4; i2++) {
        int n0 = wA * 8 + i2 * 2;
        base1p[i2] = pk(rowL[n0] * q1f + bg1f, rowL[n0 + 1] * q1f + bg1f);
    }
    float m1[3][8], a1[8];
    #pragma unroll
    for (int i = 0; i < 8; i++) { m1[0][i] = m1[1][i] = m1[2][i] = a1[i] = 0.f; }

    u64 p2p[2], base2p[4][2];
    #pragma unroll
    for (int cp = 0; cp < 2; cp++) {
        int c = c0 + 2 * cp;
        p2p[cp] = pk(sm[SM_P2 + c], sm[SM_P2 + c + 1]);
        float q2a = sm[SM_Q2 + c], q2b = sm[SM_Q2 + c + 1];
        float bga = sm[SM_BG2 + c], bgb = sm[SM_BG2 + c + 1];
        #pragma unroll
        for (int r = 0; r < 4; r++)
            base2p[r][cp] = pk(rowL[nR + r] * q2a + bga, rowL[nR + r] * q2b + bgb);
    }
    float m2[3][16], a2[16];
    #pragma unroll
    for (int e = 0; e < 16; e++) { m2[0][e] = m2[1][e] = m2[2][e] = a2[e] = 0.f; }

    const uint32_t bS1[3] = { smb + SM_S1_0 * 4, smb + SM_S1_1 * 4, smb + SM_S1_2 * 4 };
    const uint32_t bPT[3] = { smb + SM_PT_0 * 4, smb + SM_PT_1 * 4, smb + SM_PT_2 * 4 };
    const uint32_t bST = smb + SM_ST * 4;
    const uint32_t wAddr = smb + SM_WG2 * 4 + c0 * 4;
    const uint32_t lA2 = smb + SM_LT * 4 + nq4;

    #define PHASE1(T, S1OFF)                                                      \
    {                                                                             \
        const float ct1 = coef[(T)];                                              \
        const uint32_t stR = bST + (T) * 256;                                     \
        _Pragma("unroll")                                                         \
        for (int i2 = 0; i2 < 4; i2++) {                                          \
            int n0 = wA * 8 + i2 * 2;                                             \
            u64 Sp = lds1(stR + n0 * 4);                                          \
            u64 curp = f2(Sp, p1dup, base1p[i2]);                                 \
            float c0_, c1_; upk(curp, c0_, c1_);                                  \
            _Pragma("unroll")                                                     \
            for (int h = 0; h < 2; h++) {                                         \
                float cur = h ? c1_ : c0_;                                        \
                int u = i2 * 2 + h;                                               \
                float s = 0.f;                                                    \
                s += lif_step(m1[0][u], cur, 0.80f, 0.8f);                        \
                s += lif_step(m1[1][u], cur, 0.90f, 1.0f);                        \
                s += lif_step(m1[2][u], cur, 0.95f, 1.5f);                        \
                a1[u] += ct1 * s;                                                 \
                sm[(S1OFF) + (n0 + h) * 32 + lane] = s;                           \
            }                                                                     \
        }                                                                         \
    }

    for (int g = 0; g < 5; g++) {
        const int t0 = g * 3;
        PHASE1(t0 + 0, SM_S1_0);
        PHASE1(t0 + 1, SM_S1_1);
        PHASE1(t0 + 2, SM_S1_2);
        __syncthreads();

        // ---- phase 2 grouped: 256 threads, 4n x 2j x 3t tiles ----
        {
            u64 A[3][2][2];
            #pragma unroll
            for (int tt = 0; tt < 3; tt++)
                #pragma unroll
                for (int jj = 0; jj < 2; jj++) { A[tt][jj][0] = 0; A[tt][jj][1] = 0; }
            #pragma unroll 8
            for (int m = 0; m < 64; m++) {
                u64 l01, l23;
                lds2(l01, l23, lA2 + m * 256);
                #pragma unroll
                for (int tt = 0; tt < 3; tt++) {
                    u64 sv = lds1(bS1[tt] + m * 128 + jp * 4);
                    float sa, sb; upk(sv, sa, sb);
                    u64 da = pk(sa, sa), db = pk(sb, sb);
                    A[tt][0][0] = f2(l01, da, A[tt][0][0]);
                    A[tt][0][1] = f2(l23, da, A[tt][0][1]);
                    A[tt][1][0] = f2(l01, db, A[tt][1][0]);
                    A[tt][1][1] = f2(l23, db, A[tt][1][1]);
                }
            }
            #pragma unroll
            for (int tt = 0; tt < 3; tt++)
                #pragma unroll
                for (int jj = 0; jj < 2; jj++)
                    sts2(bPT[tt] + (jp + jj) * 256 + nq4, A[tt][jj][0], A[tt][jj][1]);
        }
        __syncthreads();

        // ---- phase 3 grouped (unchanged from R12/R15) ----
        {
            u64 C[3][4][2];
            #pragma unroll
            for (int tt = 0; tt < 3; tt++)
                #pragma unroll
                for (int r = 0; r < 4; r++) { C[tt][r][0] = 0; C[tt][r][1] = 0; }
            #pragma unroll 4
            for (int f = 0; f < 32; f++) {
                u64 w01, w23;
                lds2(w01, w23, wAddr + f * 256);
                #pragma unroll
                for (int tt = 0; tt < 3; tt++) {
                    u64 p01, p23;
                    lds2(p01, p23, bPT[tt] + nR * 4 + f * 256);
                    float pa, pb, pc_, pd_;
                    upk(p01, pa, pb); upk(p23, pc_, pd_);
                    u64 da = pk(pa, pa), db = pk(pb, pb);
                    u64 dc = pk(pc_, pc_), dd = pk(pd_, pd_);
                    C[tt][0][0] = f2(da, w01, C[tt][0][0]);  C[tt][0][1] = f2(da, w23, C[tt][0][1]);
                    C[tt][1][0] = f2(db, w01, C[tt][1][0]);  C[tt][1][1] = f2(db, w23, C[tt][1][1]);
                    C[tt][2][0] = f2(dc, w01, C[tt][2][0]);  C[tt][2][1] = f2(dc, w23, C[tt][2][1]);
                    C[tt][3][0] = f2(dd, w01, C[tt][3][0]);  C[tt][3][1] = f2(dd, w23, C[tt][3][1]);
                }
            }
            #pragma unroll
            for (int tt = 0; tt < 3; tt++) {
                const int t = t0 + tt;
                const float ct = coef[t];
                u64 sc01, sc23;
                lds2(sc01, sc23, bST + t * 256 + nR * 4);
                float scv[4];
                upk(sc01, scv[0], scv[1]); upk(sc23, scv[2], scv[3]);
                #pragma unroll
                for (int r = 0; r < 4; r++) {
                    u64 scd = pk(scv[r], scv[r]);
                    #pragma unroll
                    for (int cp = 0; cp < 2; cp++) {
                        u64 curp = f2(scd, p2p[cp], add2(C[tt][r][cp], base2p[r][cp]));
                        float cl, ch; upk(curp, cl, ch);
                        #pragma unroll
                        for (int h = 0; h < 2; h++) {
                            float cur = h ? ch : cl;
                            int e = r * 4 + cp * 2 + h;
                            float s = 0.f;
                            s += lif_step(m2[0][e], cur, 0.80f, 0.8f);
                            s += lif_step(m2[1][e], cur, 0.90f, 1.0f);
                            s += lif_step(m2[2][e], cur, 0.95f, 1.5f);
                            a2[e] += ct * s;
                        }
                    }
                }
            }
        }
    }
    __syncthreads();

    // epilogue
    #pragma unroll
    for (int i = 0; i < 8; i++)
        sm[SM_PT_0 + lane * 64 + wA * 8 + i] = a1[i];
    #pragma unroll
    for (int k = 0; k < 8; k++)
        sm[SM_S1_0 + tid + k * 256] = Ws2[tid + k * 256];
    if (tid < 64) {
        float acc = 0.f;
        #pragma unroll
        for (int t = 0; t < TSTEPS; t++) acc += coef[t] * Xs[t * 64 + tid];
        axs[tid] = acc;
    }
    __syncthreads();

    u64 D[4][2];
    #pragma unroll
    for (int r = 0; r < 4; r++)
        #pragma unroll
        for (int cp = 0; cp < 2; cp++)
            D[r][cp] = pk(a2[r * 4 + cp * 2], a2[r * 4 + cp * 2 + 1]);

    const uint32_t pA0 = bPT[0] + nR * 4;
    const uint32_t wsA = smb + SM_S1_0 * 4 + c0 * 4;
    #pragma unroll
    for (int f = 0; f < 32; f++) {
        u64 p01, p23, w01, w23;
        lds2(p01, p23, pA0 + f * 256);
        lds2(w01, w23, wsA + f * 256);
        float pa, pb, pc_, pd_;
        upk(p01, pa, pb); upk(p23, pc_, pd_);
        u64 da = pk(pa, pa), db = pk(pb, pb);
        u64 dc = pk(pc_, pc_), dd = pk(pd_, pd_);
        D[0][0] = f2(da, w01, D[0][0]);  D[0][1] = f2(da, w23, D[0][1]);
        D[1][0] = f2(db, w01, D[1][0]);  D[1][1] = f2(db, w23, D[1][1]);
        D[2][0] = f2(dc, w01, D[2][0]);  D[2][1] = f2(dc, w23, D[2][1]);
        D[3][0] = f2(dd, w01, D[3][0]);  D[3][1] = f2(dd, w23, D[3][1]);
    }
    const float csum = coef[15];
    float ps2c[4], qs2c[4];
    #pragma unroll
    for (int c = 0; c < 4; c++) {
        ps2c[c] = sm[SM_PS2 + c0 + c];
        qs2c[c] = sm[SM_QS2 + c0 + c];
    }
    #pragma unroll
    for (int r = 0; r < 4; r++) {
        float v[4];
        upk(D[r][0], v[0], v[1]);
        upk(D[r][1], v[2], v[3]);
        int n = nR + r;
        float axv = axs[n];
        float4 o;
        o.x = v[0] + axv * ps2c[0] + csum * qs2c[0];
        o.y = v[1] + axv * ps2c[1] + csum * qs2c[1];
        o.z = v[2] + axv * ps2c[2] + csum * qs2c[2];
        o.w = v[3] + axv * ps2c[3] + csum * qs2c[3];
        *(float4*)(g_dp + (size_t)b * 4096 + n * 64 + c0) = o;
    }
    #undef PHASE1
}

// ---------------------------------------------------------------------------
// decoder split-K (R15): 64-row CTAs, 8r x 4c tiles, 8 k-splits.
__global__ void __launch_bounds__(256)
decoder_partial(const float* __restrict__ Wc1, float* __restrict__ part) {
    __shared__ float Wc1s[64 * 128];
    __shared__ float dpT[64 * 64];

    const int tid = threadIdx.x;
    const int b0 = blockIdx.x * 64;
    const int ks = blockIdx.y;
    const int kbase = ks * 512;

    const uint32_t bW  = (uint32_t)__cvta_generic_to_shared(Wc1s);
    const uint32_t bDP = (uint32_t)__cvta_generic_to_shared(dpT);

    const int rg = (tid & 7) * 8;
    const int jc = (tid >> 3) * 4;
    u64 hp[4][4];
    #pragma unroll
    for (int p = 0; p < 4; p++)
        #pragma unroll
        for (int c = 0; c < 4; c++) hp[p][c] = 0;

    for (int k0 = kbase; k0 < kbase + 512; k0 += 64) {
        __syncthreads();
        #pragma unroll
        for (int p = 0; p < 8; p++) {
            int f4 = tid + p * 256;
            int kk = f4 >> 5, jq = f4 & 31;
            *(float4*)(Wc1s + kk * 128 + jq * 4) =
                *(const float4*)(Wc1 + (size_t)(k0 + kk) * 128 + jq * 4);
        }
        {
            int r = tid >> 2, kq = tid & 3;
            #pragma unroll
            for (int q = 0; q < 4; q++) {
                int kk = kq * 16 + q * 4;
                float4 v = *(const float4*)(g_dp + (size_t)(b0 + r) * 4096 + k0 + kk);
                dpT[(kk + 0) * 64 + r] = v.x;
                dpT[(kk + 1) * 64 + r] = v.y;
                dpT[(kk + 2) * 64 + r] = v.z;
                dpT[(kk + 3) * 64 + r] = v.w;
            }
        }
        __syncthreads();
        #pragma unroll 8
        for (int kk = 0; kk < 64; kk++) {
            u64 d0, d1, d2, d3;
            lds2(d0, d1, bDP + kk * 256 + rg * 4);
            lds2(d2, d3, bDP + kk * 256 + rg * 4 + 16);
            u64 wp0 = lds1(bW + kk * 512 + jc * 4);
            u64 wp1 = lds1(bW + kk * 512 + jc * 4 + 8);
            float w0, w1, w2, w3;
            upk(wp0, w0, w1); upk(wp1, w2, w3);
            u64 dw0 = pk(w0, w0), dw1 = pk(w1, w1);
            u64 dw2 = pk(w2, w2), dw3 = pk(w3, w3);
            hp[0][0] = f2(d0, dw0, hp[0][0]);  hp[0][1] = f2(d0, dw1, hp[0][1]);
            hp[0][2] = f2(d0, dw2, hp[0][2]);  hp[0][3] = f2(d0, dw3, hp[0][3]);
            hp[1][0] = f2(d1, dw0, hp[1][0]);  hp[1][1] = f2(d1, dw1, hp[1][1]);
            hp[1][2] = f2(d1, dw2, hp[1][2]);  hp[1][3] = f2(d1, dw3, hp[1][3]);
            hp[2][0] = f2(d2, dw0, hp[2][0]);  hp[2][1] = f2(d2, dw1, hp[2][1]);
            hp[2][2] = f2(d2, dw2, hp[2][2]);  hp[2][3] = f2(d2, dw3, hp[2][3]);
            hp[3][0] = f2(d3, dw0, hp[3][0]);  hp[3][1] = f2(d3, dw1, hp[3][1]);
            hp[3][2] = f2(d3, dw2, hp[3][2]);  hp[3][3] = f2(d3, dw3, hp[3][3]);
        }
    }
    #pragma unroll
    for (int p = 0; p < 4; p++) {
        float lo[4], hi[4];
        #pragma unroll
        for (int c = 0; c < 4; c++) upk(hp[p][c], lo[c], hi[c]);
        int row0 = rg + p * 2;
        float* o0 = part + ((size_t)ks * 2048 + (b0 + row0 + 0)) * 128 + jc;
        float* o1 = part + ((size_t)ks * 2048 + (b0 + row0 + 1)) * 128 + jc;
        *(float4*)o0 = make_float4(lo[0], lo[1], lo[2], lo[3]);
        *(float4*)o1 = make_float4(hi[0], hi[1], hi[2], hi[3]);
    }
}

__global__ void __launch_bounds__(256)
decoder_finish(const float* __restrict__ part, const float* __restrict__ bc1,
               const float* __restrict__ Wc2, const float* __restrict__ bc2,
               float* __restrict__ out) {
    __shared__ float hs[16 * 128];
    __shared__ float Wc2s[128 * 4];

    const int tid = threadIdx.x;
    const int b0 = blockIdx.x * 16;
    for (int i = tid; i < 512; i += 256) Wc2s[i] = Wc2[i];

    const int j = tid & 127, rh = tid >> 7;
    const float bb = bc1[j];
    #pragma unroll
    for (int r = 0; r < 8; r++) {
        int row = rh * 8 + r;
        size_t off = (size_t)(b0 + row) * 128 + j;
        float v = bb;
        #pragma unroll
        for (int ks = 0; ks < 8; ks++)
            v += part[(size_t)ks * 2048 * 128 + off];
        hs[row * 128 + j] = v > 0.f ? v : 0.f;
    }
    __syncthreads();
    if (tid < 64) {
        int r = tid >> 2, c = tid & 3;
        float acc = bc2[c];
        #pragma unroll 8
        for (int jj = 0; jj < 128; jj++) acc += hs[r * 128 + jj] * Wc2s[jj * 4 + c];
        out[(b0 + r) * 4 + c] = acc;
    }
}

// ---------------------------------------------------------------------------
extern "C" void kernel_launch(void* const* d_in, const int* in_sizes, int n_in,
                              void* d_out, int out_size) {
    const float* L     = (const float*)d_in[0];
    const float* X     = (const float*)d_in[1];
    const float* Wproj = (const float*)d_in[2];
    const float* bproj = (const float*)d_in[3];
    const float* Wg1   = (const float*)d_in[4];
    const float* bg1   = (const float*)d_in[5];
    const float* Ws1   = (const float*)d_in[6];
    const float* bs1   = (const float*)d_in[7];
    const float* Wg2   = (const float*)d_in[8];
    const float* bg2   = (const float*)d_in[9];
    const float* Ws2   = (const float*)d_in[10];
    const float* bs2   = (const float*)d_in[11];
    const float* Wc1   = (const float*)d_in[12];
    const float* bc1   = (const float*)d_in[13];
    const float* Wc2   = (const float*)d_in[14];
    const float* bc2   = (const float*)d_in[15];
    float* out = (float*)d_out;

    int B = in_sizes[0] / 4096;
    if (B > 2048) B = 2048;

    static const size_t smem_bytes = SM_TOTAL * sizeof(float);
    cudaFuncSetAttribute(main_kernel, cudaFuncAttributeMaxDynamicSharedMemorySize,
                         (int)smem_bytes);

    float* part;
    cudaGetSymbolAddress((void**)&part, g_part);

    main_kernel<<<B, 256, smem_bytes>>>(L, X, Wproj, bproj, Wg1, bg1, Ws1, bs1,
                                        Wg2, bg2, Ws2, bs2);
    dim3 gridA(B / 64, 8);
    decoder_partial<<<gridA, 256>>>(Wc1, part);
    decoder_finish<<<B / 16, 256>>>(part, bc1, Wc2, bc2, out);
}

// round 17
// speedup vs baseline: 1.0389x; 1.0389x over previous
#include <cuda_runtime.h>
#include <cstdint>

#define TSTEPS 15
__device__ float g_dp[2048 * 4096];
__device__ float g_part[8 * 2048 * 128];

typedef unsigned long long u64;
__device__ __forceinline__ u64 pk(float lo, float hi) {
    u64 d; asm("mov.b64 %0,{%1,%2};" : "=l"(d) : "f"(lo), "f"(hi)); return d;
}
__device__ __forceinline__ void upk(u64 v, float& lo, float& hi) {
    asm("mov.b64 {%0,%1},%2;" : "=f"(lo), "=f"(hi) : "l"(v));
}
__device__ __forceinline__ u64 f2(u64 a, u64 b, u64 c) {
    u64 d; asm("fma.rn.f32x2 %0,%1,%2,%3;" : "=l"(d) : "l"(a), "l"(b), "l"(c)); return d;
}
__device__ __forceinline__ u64 add2(u64 a, u64 b) {
    u64 d; asm("add.rn.f32x2 %0,%1,%2;" : "=l"(d) : "l"(a), "l"(b)); return d;
}
__device__ __forceinline__ void lds2(u64& a, u64& b, uint32_t addr) {
    asm volatile("ld.shared.v2.u64 {%0,%1},[%2];" : "=l"(a), "=l"(b) : "r"(addr));
}
__device__ __forceinline__ u64 lds1(uint32_t addr) {
    u64 a; asm volatile("ld.shared.b64 %0,[%1];" : "=l"(a) : "r"(addr)); return a;
}
__device__ __forceinline__ void sts2(uint32_t addr, u64 a, u64 b) {
    asm volatile("st.shared.v2.u64 [%0],{%1,%2};" :: "r"(addr), "l"(a), "l"(b));
}
__device__ __forceinline__ float lif_step(float& m, float cur, float beta, float thr) {
    float r = (m > thr) ? thr : 0.f;
    m = beta * m + (cur - r);
    return (m > thr) ? 1.f : 0.f;
}

// smem float offsets (R12/R15 map)
#define SM_LT    0
#define SM_S1_0  4096
#define SM_S1_1  6144
#define SM_S1_2  8192
#define SM_PT_0  10240
#define SM_PT_1  12288
#define SM_PT_2  14336
#define SM_WG2   16384
#define SM_ST    18432
#define SM_XS    19456
#define SM_ROWL  20416
#define SM_AX    20480
#define SM_P1    20544
#define SM_Q1    20576
#define SM_BG1   20608
#define SM_PS1   20640
#define SM_CS1   20672
#define SM_P2    20704
#define SM_Q2    20768
#define SM_BG2   20832
#define SM_PS2   20896
#define SM_QS2   20960
#define SM_COEF  21024
#define SM_TOTAL 21040

__global__ void __launch_bounds__(256, 1)
main_kernel(const float* __restrict__ L, const float* __restrict__ X,
            const float* __restrict__ Wproj, const float* __restrict__ bproj,
            const float* __restrict__ Wg1, const float* __restrict__ bg1,
            const float* __restrict__ Ws1, const float* __restrict__ bs1,
            const float* __restrict__ Wg2, const float* __restrict__ bg2,
            const float* __restrict__ Ws2, const float* __restrict__ bs2) {
    extern __shared__ float sm[];
    const uint32_t smb = (uint32_t)__cvta_generic_to_shared(sm);
    float* Lt = sm + SM_LT; float* Xs = sm + SM_XS; float* St = sm + SM_ST;
    float* rowL = sm + SM_ROWL; float* axs = sm + SM_AX; float* coef = sm + SM_COEF;

    const int tid = threadIdx.x;
    const int b = blockIdx.x;
    const float* Lb = L + (size_t)b * 4096;
    const float* Xb = X + (size_t)b * (TSTEPS * 64);

    {   // Lt transpose
        int n = tid >> 2, m0 = (tid & 3) * 16;
        #pragma unroll
        for (int q = 0; q < 4; q++) {
            float4 v = *(const float4*)(Lb + n * 64 + m0 + q * 4);
            Lt[(m0 + q * 4 + 0) * 64 + n] = v.x;
            Lt[(m0 + q * 4 + 1) * 64 + n] = v.y;
            Lt[(m0 + q * 4 + 2) * 64 + n] = v.z;
            Lt[(m0 + q * 4 + 3) * 64 + n] = v.w;
        }
    }
    for (int i = tid; i < TSTEPS * 64; i += 256) Xs[i] = Xb[i];
    #pragma unroll
    for (int k = 0; k < 8; k++)
        sm[SM_WG2 + tid + k * 256] = Wg2[tid + k * 256];
    if (tid < 32) {
        float p1 = 0.f, q1 = 0.f, ps1 = 0.f, cs1 = 0.f;
        #pragma unroll
        for (int k = 0; k < 16; k++) {
            p1  += Wproj[k] * Wg1[k * 32 + tid];
            q1  += bproj[k] * Wg1[k * 32 + tid];
            ps1 += Wproj[k] * Ws1[k * 32 + tid];
            cs1 += bproj[k] * Ws1[k * 32 + tid];
        }
        cs1 += bs1[tid];
        sm[SM_P1 + tid] = p1; sm[SM_Q1 + tid] = q1;
        sm[SM_PS1 + tid] = ps1; sm[SM_CS1 + tid] = cs1;
        sm[SM_BG1 + tid] = bg1[tid];
    }
    if (tid == 32) {
        float pw[TSTEPS]; pw[0] = 1.f;
        for (int k = 1; k < TSTEPS; k++) pw[k] = pw[k - 1] * 0.9f;
        float cs = 0.f;
        for (int tau = 0; tau < TSTEPS; tau++) {
            float late = 0.f, early = 0.f;
            for (int s = 10; s < 15; s++) if (s >= tau) late += pw[s - tau];
            for (int s = 0; s < 5; s++) if (s >= tau) early += pw[s - tau];
            float c = 0.2f * (late - early);
            coef[tau] = c; cs += c;
        }
        coef[15] = cs;
    }
    __syncthreads();

    if (tid < 64) {
        float p2 = 0.f, q2 = 0.f, ps2 = 0.f, qs2 = 0.f;
        #pragma unroll
        for (int f = 0; f < 32; f++) {
            float a = sm[SM_PS1 + f], c = sm[SM_CS1 + f];
            p2 += a * Wg2[f * 64 + tid]; q2 += c * Wg2[f * 64 + tid];
            ps2 += a * Ws2[f * 64 + tid]; qs2 += c * Ws2[f * 64 + tid];
        }
        qs2 += bs2[tid];
        sm[SM_P2 + tid] = p2; sm[SM_Q2 + tid] = q2;
        sm[SM_BG2 + tid] = bg2[tid];
        sm[SM_PS2 + tid] = ps2; sm[SM_QS2 + tid] = qs2;
    }
    #pragma unroll
    for (int k = 0; k < 4; k++) {
        int idx = tid + k * 256;
        int n = idx & 63, tt = idx >> 6;
        float acc = 0.f;
        if (tt < TSTEPS) {
            const float* xr = Xs + tt * 64;
            #pragma unroll 8
            for (int m = 0; m < 64; m++) acc += Lt[m * 64 + n] * xr[m];
            St[tt * 64 + n] = acc;
        } else {
            #pragma unroll 8
            for (int m = 0; m < 64; m++) acc += Lt[m * 64 + n];
            rowL[n] = acc;
        }
    }
    __syncthreads();

    const int lane = tid & 31, wA = tid >> 5;
    const int nR = (wA & 1) * 32 + (lane & 7) * 4;
    const int c0 = (wA >> 1) * 16 + (lane >> 3) * 4;
    const int nq4 = (tid & 15) * 16;
    const int jq  = tid >> 4;

    const float p1f = sm[SM_P1 + lane], q1f = sm[SM_Q1 + lane], bg1f = sm[SM_BG1 + lane];
    const u64 p1dup = pk(p1f, p1f);
    u64 base1p[4];
    #pragma unroll
    for (int i2 = 0; i2 < 4; i2++) {
        int n0 = wA * 8 + i2 * 2;
        base1p[i2] = pk(rowL[n0] * q1f + bg1f, rowL[n0 + 1] * q1f + bg1f);
    }
    float m1[3][8], a1[8];
    #pragma unroll
    for (int i = 0; i < 8; i++) { m1[0][i] = m1[1][i] = m1[2][i] = a1[i] = 0.f; }

    u64 p2p[2], base2p[4][2];
    #pragma unroll
    for (int cp = 0; cp < 2; cp++) {
        int c = c0 + 2 * cp;
        p2p[cp] = pk(sm[SM_P2 + c], sm[SM_P2 + c + 1]);
        float q2a = sm[SM_Q2 + c], q2b = sm[SM_Q2 + c + 1];
        float bga = sm[SM_BG2 + c], bgb = sm[SM_BG2 + c + 1];
        #pragma unroll
        for (int r = 0; r < 4; r++)
            base2p[r][cp] = pk(rowL[nR + r] * q2a + bga, rowL[nR + r] * q2b + bgb);
    }
    float m2[3][16], a2[16];
    #pragma unroll
    for (int e = 0; e < 16; e++) { m2[0][e] = m2[1][e] = m2[2][e] = a2[e] = 0.f; }

    const uint32_t bS1[3] = { smb + SM_S1_0 * 4, smb + SM_S1_1 * 4, smb + SM_S1_2 * 4 };
    const uint32_t bPT[3] = { smb + SM_PT_0 * 4, smb + SM_PT_1 * 4, smb + SM_PT_2 * 4 };
    const uint32_t bST = smb + SM_ST * 4;
    const uint32_t wAddr = smb + SM_WG2 * 4 + c0 * 4;
    const uint32_t lA2 = smb + SM_LT * 4 + nq4;

    #define PHASE1(T, S1OFF)                                                      \
    {                                                                             \
        const float ct1 = coef[(T)];                                              \
        const uint32_t stR = bST + (T) * 256;                                     \
        _Pragma("unroll")                                                         \
        for (int i2 = 0; i2 < 4; i2++) {                                          \
            int n0 = wA * 8 + i2 * 2;                                             \
            u64 Sp = lds1(stR + n0 * 4);                                          \
            u64 curp = f2(Sp, p1dup, base1p[i2]);                                 \
            float c0_, c1_; upk(curp, c0_, c1_);                                  \
            _Pragma("unroll")                                                     \
            for (int h = 0; h < 2; h++) {                                         \
                float cur = h ? c1_ : c0_;                                        \
                int u = i2 * 2 + h;                                               \
                float s = 0.f;                                                    \
                s += lif_step(m1[0][u], cur, 0.80f, 0.8f);                        \
                s += lif_step(m1[1][u], cur, 0.90f, 1.0f);                        \
                s += lif_step(m1[2][u], cur, 0.95f, 1.5f);                        \
                a1[u] += ct1 * s;                                                 \
                sm[(S1OFF) + (n0 + h) * 32 + lane] = s;                           \
            }                                                                     \
        }                                                                         \
    }

    for (int g = 0; g < 5; g++) {
        const int t0 = g * 3;
        PHASE1(t0 + 0, SM_S1_0);
        PHASE1(t0 + 1, SM_S1_1);
        PHASE1(t0 + 2, SM_S1_2);
        __syncthreads();

        if (tid < 128) {
            u64 A0[3][4], A1[3][4];
            #pragma unroll
            for (int tt = 0; tt < 3; tt++)
                #pragma unroll
                for (int c = 0; c < 4; c++) { A0[tt][c] = 0; A1[tt][c] = 0; }
            const uint32_t sB0 = bS1[0] + jq * 16;
            const uint32_t sB1 = bS1[1] + jq * 16;
            const uint32_t sB2 = bS1[2] + jq * 16;
            #pragma unroll 8
            for (int m = 0; m < 64; m++) {
                u64 l01, l23;
                lds2(l01, l23, lA2 + m * 256);
                #pragma unroll
                for (int tt = 0; tt < 3; tt++) {
                    uint32_t sA = (tt == 0 ? sB0 : (tt == 1 ? sB1 : sB2)) + m * 128;
                    u64 s01, s23;
                    lds2(s01, s23, sA);
                    float sa, sb, sc_, sd_;
                    upk(s01, sa, sb); upk(s23, sc_, sd_);
                    u64 d0 = pk(sa, sa), d1 = pk(sb, sb);
                    u64 d2 = pk(sc_, sc_), d3 = pk(sd_, sd_);
                    A0[tt][0] = f2(l01, d0, A0[tt][0]);  A1[tt][0] = f2(l23, d0, A1[tt][0]);
                    A0[tt][1] = f2(l01, d1, A0[tt][1]);  A1[tt][1] = f2(l23, d1, A1[tt][1]);
                    A0[tt][2] = f2(l01, d2, A0[tt][2]);  A1[tt][2] = f2(l23, d2, A1[tt][2]);
                    A0[tt][3] = f2(l01, d3, A0[tt][3]);  A1[tt][3] = f2(l23, d3, A1[tt][3]);
                }
            }
            #pragma unroll
            for (int tt = 0; tt < 3; tt++)
                #pragma unroll
                for (int c = 0; c < 4; c++)
                    sts2(bPT[tt] + (jq * 4 + c) * 256 + nq4, A0[tt][c], A1[tt][c]);
        }
        __syncthreads();

        {
            u64 C[3][4][2];
            #pragma unroll
            for (int tt = 0; tt < 3; tt++)
                #pragma unroll
                for (int r = 0; r < 4; r++) { C[tt][r][0] = 0; C[tt][r][1] = 0; }
            #pragma unroll 4
            for (int f = 0; f < 32; f++) {
                u64 w01, w23;
                lds2(w01, w23, wAddr + f * 256);
                #pragma unroll
                for (int tt = 0; tt < 3; tt++) {
                    u64 p01, p23;
                    lds2(p01, p23, bPT[tt] + nR * 4 + f * 256);
                    float pa, pb, pc_, pd_;
                    upk(p01, pa, pb); upk(p23, pc_, pd_);
                    u64 da = pk(pa, pa), db = pk(pb, pb);
                    u64 dc = pk(pc_, pc_), dd = pk(pd_, pd_);
                    C[tt][0][0] = f2(da, w01, C[tt][0][0]);  C[tt][0][1] = f2(da, w23, C[tt][0][1]);
                    C[tt][1][0] = f2(db, w01, C[tt][1][0]);  C[tt][1][1] = f2(db, w23, C[tt][1][1]);
                    C[tt][2][0] = f2(dc, w01, C[tt][2][0]);  C[tt][2][1] = f2(dc, w23, C[tt][2][1]);
                    C[tt][3][0] = f2(dd, w01, C[tt][3][0]);  C[tt][3][1] = f2(dd, w23, C[tt][3][1]);
                }
            }
            #pragma unroll
            for (int tt = 0; tt < 3; tt++) {
                const int t = t0 + tt;
                const float ct = coef[t];
                u64 sc01, sc23;
                lds2(sc01, sc23, bST + t * 256 + nR * 4);
                float scv[4];
                upk(sc01, scv[0], scv[1]); upk(sc23, scv[2], scv[3]);
                #pragma unroll
                for (int r = 0; r < 4; r++) {
                    u64 scd = pk(scv[r], scv[r]);
                    #pragma unroll
                    for (int cp = 0; cp < 2; cp++) {
                        u64 curp = f2(scd, p2p[cp], add2(C[tt][r][cp], base2p[r][cp]));
                        float cl, ch; upk(curp, cl, ch);
                        #pragma unroll
                        for (int h = 0; h < 2; h++) {
                            float cur = h ? ch : cl;
                            int e = r * 4 + cp * 2 + h;
                            float s = 0.f;
                            s += lif_step(m2[0][e], cur, 0.80f, 0.8f);
                            s += lif_step(m2[1][e], cur, 0.90f, 1.0f);
                            s += lif_step(m2[2][e], cur, 0.95f, 1.5f);
                            a2[e] += ct * s;
                        }
                    }
                }
            }
        }
    }
    __syncthreads();

    // epilogue
    #pragma unroll
    for (int i = 0; i < 8; i++)
        sm[SM_PT_0 + lane * 64 + wA * 8 + i] = a1[i];
    #pragma unroll
    for (int k = 0; k < 8; k++)
        sm[SM_S1_0 + tid + k * 256] = Ws2[tid + k * 256];
    if (tid < 64) {
        float acc = 0.f;
        #pragma unroll
        for (int t = 0; t < TSTEPS; t++) acc += coef[t] * Xs[t * 64 + tid];
        axs[tid] = acc;
    }
    __syncthreads();

    u64 D[4][2];
    #pragma unroll
    for (int r = 0; r < 4; r++)
        #pragma unroll
        for (int cp = 0; cp < 2; cp++)
            D[r][cp] = pk(a2[r * 4 + cp * 2], a2[r * 4 + cp * 2 + 1]);

    const uint32_t pA0 = bPT[0] + nR * 4;
    const uint32_t wsA = smb + SM_S1_0 * 4 + c0 * 4;
    #pragma unroll
    for (int f = 0; f < 32; f++) {
        u64 p01, p23, w01, w23;
        lds2(p01, p23, pA0 + f * 256);
        lds2(w01, w23, wsA + f * 256);
        float pa, pb, pc_, pd_;
        upk(p01, pa, pb); upk(p23, pc_, pd_);
        u64 da = pk(pa, pa), db = pk(pb, pb);
        u64 dc = pk(pc_, pc_), dd = pk(pd_, pd_);
        D[0][0] = f2(da, w01, D[0][0]);  D[0][1] = f2(da, w23, D[0][1]);
        D[1][0] = f2(db, w01, D[1][0]);  D[1][1] = f2(db, w23, D[1][1]);
        D[2][0] = f2(dc, w01, D[2][0]);  D[2][1] = f2(dc, w23, D[2][1]);
        D[3][0] = f2(dd, w01, D[3][0]);  D[3][1] = f2(dd, w23, D[3][1]);
    }
    const float csum = coef[15];
    float ps2c[4], qs2c[4];
    #pragma unroll
    for (int c = 0; c < 4; c++) {
        ps2c[c] = sm[SM_PS2 + c0 + c];
        qs2c[c] = sm[SM_QS2 + c0 + c];
    }
    #pragma unroll
    for (int r = 0; r < 4; r++) {
        float v[4];
        upk(D[r][0], v[0], v[1]);
        upk(D[r][1], v[2], v[3]);
        int n = nR + r;
        float axv = axs[n];
        float4 o;
        o.x = v[0] + axv * ps2c[0] + csum * qs2c[0];
        o.y = v[1] + axv * ps2c[1] + csum * qs2c[1];
        o.z = v[2] + axv * ps2c[2] + csum * qs2c[2];
        o.w = v[3] + axv * ps2c[3] + csum * qs2c[3];
        *(float4*)(g_dp + (size_t)b * 4096 + n * 64 + c0) = o;
    }
    #undef PHASE1
}

// ---------------------------------------------------------------------------
// decoder split-K v3: 128 threads, 64-row CTAs, 8r x 8c tiles, 8 k-splits.
// grid (32, 8). 1.0 B/MAC requested smem; 48KB smem -> multi-CTA residency.
__global__ void __launch_bounds__(128)
decoder_partial(const float* __restrict__ Wc1, float* __restrict__ part) {
    __shared__ float Wc1s[64 * 128];   // 32 KB
    __shared__ float dpT[64 * 64];     // 16 KB  dpT[k][row]

    const int tid = threadIdx.x;
    const int b0 = blockIdx.x * 64;
    const int ks = blockIdx.y;
    const int kbase = ks * 512;

    const uint32_t bW  = (uint32_t)__cvta_generic_to_shared(Wc1s);
    const uint32_t bDP = (uint32_t)__cvta_generic_to_shared(dpT);

    const int rg = (tid & 7) * 8;        // 8-row group base (0..56)
    const int jc = (tid >> 3) * 8;       // 8-col base (0..120)
    u64 hp[4][8];                        // [rowpair][col]
    #pragma unroll
    for (int p = 0; p < 4; p++)
        #pragma unroll
        for (int c = 0; c < 8; c++) hp[p][c] = 0;

    for (int k0 = kbase; k0 < kbase + 512; k0 += 64) {
        __syncthreads();
        #pragma unroll
        for (int p = 0; p < 16; p++) {   // Wc1 chunk [64k][128j]
            int f4 = tid + p * 128;
            int kk = f4 >> 5, jq = f4 & 31;
            *(float4*)(Wc1s + kk * 128 + jq * 4) =
                *(const float4*)(Wc1 + (size_t)(k0 + kk) * 128 + jq * 4);
        }
        {                                 // dp chunk transposed [64k][64row]
            int r = tid >> 1, kq = tid & 1;
            #pragma unroll
            for (int q = 0; q < 8; q++) {
                int kk = kq * 32 + q * 4;
                float4 v = *(const float4*)(g_dp + (size_t)(b0 + r) * 4096 + k0 + kk);
                dpT[(kk + 0) * 64 + r] = v.x;
                dpT[(kk + 1) * 64 + r] = v.y;
                dpT[(kk + 2) * 64 + r] = v.z;
                dpT[(kk + 3) * 64 + r] = v.w;
            }
        }
        __syncthreads();
        #pragma unroll 4
        for (int kk = 0; kk < 64; kk++) {
            u64 d0, d1, d2, d3;
            lds2(d0, d1, bDP + kk * 256 + rg * 4);
            lds2(d2, d3, bDP + kk * 256 + rg * 4 + 16);
            u64 w01, w23, w45, w67;
            lds2(w01, w23, bW + kk * 512 + jc * 4);
            lds2(w45, w67, bW + kk * 512 + jc * 4 + 16);
            float w[8];
            upk(w01, w[0], w[1]); upk(w23, w[2], w[3]);
            upk(w45, w[4], w[5]); upk(w67, w[6], w[7]);
            #pragma unroll
            for (int c = 0; c < 8; c++) {
                u64 dw = pk(w[c], w[c]);
                hp[0][c] = f2(d0, dw, hp[0][c]);
                hp[1][c] = f2(d1, dw, hp[1][c]);
                hp[2][c] = f2(d2, dw, hp[2][c]);
                hp[3][c] = f2(d3, dw, hp[3][c]);
            }
        }
    }
    // write partials: rows rg+2p+{0,1}, cols jc..jc+7
    #pragma unroll
    for (int p = 0; p < 4; p++) {
        float lo[8], hi[8];
        #pragma unroll
        for (int c = 0; c < 8; c++) upk(hp[p][c], lo[c], hi[c]);
        int row0 = rg + p * 2;
        float* o0 = part + ((size_t)ks * 2048 + (b0 + row0 + 0)) * 128 + jc;
        float* o1 = part + ((size_t)ks * 2048 + (b0 + row0 + 1)) * 128 + jc;
        *(float4*)(o0)     = make_float4(lo[0], lo[1], lo[2], lo[3]);
        *(float4*)(o0 + 4) = make_float4(lo[4], lo[5], lo[6], lo[7]);
        *(float4*)(o1)     = make_float4(hi[0], hi[1], hi[2], hi[3]);
        *(float4*)(o1 + 4) = make_float4(hi[4], hi[5], hi[6], hi[7]);
    }
}

__global__ void __launch_bounds__(256)
decoder_finish(const float* __restrict__ part, const float* __restrict__ bc1,
               const float* __restrict__ Wc2, const float* __restrict__ bc2,
               float* __restrict__ out) {
    __shared__ float hs[16 * 128];
    __shared__ float Wc2s[128 * 4];

    const int tid = threadIdx.x;
    const int b0 = blockIdx.x * 16;
    for (int i = tid; i < 512; i += 256) Wc2s[i] = Wc2[i];

    const int j = tid & 127, rh = tid >> 7;
    const float bb = bc1[j];
    #pragma unroll
    for (int r = 0; r < 8; r++) {
        int row = rh * 8 + r;
        size_t off = (size_t)(b0 + row) * 128 + j;
        float v = bb;
        #pragma unroll
        for (int ks = 0; ks < 8; ks++)
            v += part[(size_t)ks * 2048 * 128 + off];
        hs[row * 128 + j] = v > 0.f ? v : 0.f;
    }
    __syncthreads();
    if (tid < 64) {
        int r = tid >> 2, c = tid & 3;
        float acc = bc2[c];
        #pragma unroll 8
        for (int jj = 0; jj < 128; jj++) acc += hs[r * 128 + jj] * Wc2s[jj * 4 + c];
        out[(b0 + r) * 4 + c] = acc;
    }
}

// ---------------------------------------------------------------------------
extern "C" void kernel_launch(void* const* d_in, const int* in_sizes, int n_in,
                              void* d_out, int out_size) {
    const float* L     = (const float*)d_in[0];
    const float* X     = (const float*)d_in[1];
    const float* Wproj = (const float*)d_in[2];
    const float* bproj = (const float*)d_in[3];
    const float* Wg1   = (const float*)d_in[4];
    const float* bg1   = (const float*)d_in[5];
    const float* Ws1   = (const float*)d_in[6];
    const float* bs1   = (const float*)d_in[7];
    const float* Wg2   = (const float*)d_in[8];
    const float* bg2   = (const float*)d_in[9];
    const float* Ws2   = (const float*)d_in[10];
    const float* bs2   = (const float*)d_in[11];
    const float* Wc1   = (const float*)d_in[12];
    const float* bc1   = (const float*)d_in[13];
    const float* Wc2   = (const float*)d_in[14];
    const float* bc2   = (const float*)d_in[15];
    float* out = (float*)d_out;

    int B = in_sizes[0] / 4096;
    if (B > 2048) B = 2048;

    static const size_t smem_bytes = SM_TOTAL * sizeof(float);
    cudaFuncSetAttribute(main_kernel, cudaFuncAttributeMaxDynamicSharedMemorySize,
                         (int)smem_bytes);

    float* part;
    cudaGetSymbolAddress((void**)&part, g_part);

    main_kernel<<<B, 256, smem_bytes>>>(L, X, Wproj, bproj, Wg1, bg1, Ws1, bs1,
                                        Wg2, bg2, Ws2, bs2);
    dim3 gridA(B / 64, 8);
    decoder_partial<<<gridA, 128>>>(Wc1, part);
    decoder_finish<<<B / 16, 256>>>(part, bc1, Wc2, bc2, out);
}